// round 9
// baseline (speedup 1.0000x reference)
#include <cuda_runtime.h>
#include <cuda_bf16.h>

typedef unsigned long long u64;

// Cross-block scratch (no allocations allowed -> __device__ globals)
__device__ float2 g_v[4][4096];     // 4 columns of the circuit unitary (natural order)
__device__ u64 g_sX[4][2048];       // per-column global staging, X (re) parts
__device__ u64 g_sY[4][2048];       // per-column global staging, Y (im) parts
__device__ unsigned g_cnt[4];       // per-column layer arrival counters (reset each launch)
__device__ int g_flag = 0;          // sim-done counter (target 8)
__device__ int g_done2 = 0;         // output-blocks-passed-spin counter

// ---------------- f32x2 packed helpers ----------------
__device__ __forceinline__ u64 pack2(float x, float y) {
    u64 u; asm("mov.b64 %0, {%1,%2};" : "=l"(u) : "f"(x), "f"(y)); return u;
}
__device__ __forceinline__ float2 unpack2(u64 u) {
    float2 v; asm("mov.b64 {%0,%1}, %2;" : "=f"(v.x), "=f"(v.y) : "l"(u)); return v;
}
__device__ __forceinline__ u64 swap2(u64 u) {
    float2 v = unpack2(u); return pack2(v.y, v.x);
}
__device__ __forceinline__ u64 fma2(u64 a, u64 b, u64 c) {
    u64 d; asm("fma.rn.f32x2 %0, %1, %2, %3;" : "=l"(d) : "l"(a), "l"(b), "l"(c)); return d;
}
__device__ __forceinline__ u64 mul2(u64 a, u64 b) {
    u64 d; asm("mul.rn.f32x2 %0, %1, %2;" : "=l"(d) : "l"(a), "l"(b)); return d;
}
__device__ __forceinline__ float ldcg(const float* p) {
    float v; asm volatile("ld.global.cg.f32 %0, [%1];" : "=f"(v) : "l"(p)); return v;
}
__device__ __forceinline__ void stcg64(u64* p, u64 v) {
    asm volatile("st.global.cg.b64 [%0], %1;" :: "l"(p), "l"(v));
}

struct Coef { u64 sx, sy, nsy, ox, oy, noy; };

__device__ __forceinline__ Coef ldCoef(const u64* c) {
    Coef k;
    k.sx = c[0]; k.sy = c[1]; k.nsy = c[2];
    k.ox = c[3]; k.oy = c[4]; k.noy = c[5];
    return k;
}

// new = s*a + o*p (complex, 2 packed lanes): 8 f32x2 ops
__device__ __forceinline__ void cupd(u64 X, u64 Y, u64 PX, u64 PY, const Coef& c,
                                     u64& NX, u64& NY) {
    u64 nx = mul2(c.sx, X);
    nx = fma2(c.nsy, Y, nx);
    nx = fma2(c.ox, PX, nx);
    nx = fma2(c.noy, PY, nx);
    u64 ny = mul2(c.sx, Y);
    ny = fma2(c.sy, X, ny);
    ny = fma2(c.ox, PY, ny);
    ny = fma2(c.oy, PX, ny);
    NX = nx; NY = ny;
}

// ---------------- shared memory (dynamic, ~46KB) ----------------
// coef layout per gate (18 u64): [0..5]=C0 (branch0), [6..11]=C1, [12..17]=Cp (pack)
struct SimSmem {
    u64 coef[96 * 18];
    u64 aX[1024]; u64 aY[1024];   // local transpose A staging
    u64 bX[1024]; u64 bY[1024];   // local transpose B staging
};

// ---------------------------------------------------------------------------
// Indexing: 8 sim CTAs = 4 columns x 2 halves. 512 threads, 4 amps/thread.
// Natural amp n (12 bits). Layer-start assignment:
//   lam (f32x2 lane) = n0, p (u64 pair) = n1, t0..t4 (lane) = n2..n6,
//   t5..t8 (warp) = n7..n10, r (CTA half) = n11. Wire w acts on bit 11-w.
// Per layer: gates on bits 0..6 (pack/pair/5 shfl); local transpose A swaps
// (lam,p)<->(n9,n10) -> gates 9,10; transpose B swaps (lam,p)<->(n7,n8) ->
// gates 7,8; then global staging + cross-CTA sync + gather that fuses the
// bit-11 gate (branch = r, uniform per CTA) with the CNOT perm y -> y^(y>>1).
// ---------------------------------------------------------------------------

// gate on the pair bit (in-register partner)
__device__ __forceinline__ void gate_pair(u64 AX[2], u64 AY[2], const u64* cc) {
    Coef C0 = ldCoef(cc);
    Coef C1 = ldCoef(cc + 6);
    u64 x0 = AX[0], y0 = AY[0], x1 = AX[1], y1 = AY[1];
    cupd(x0, y0, x1, y1, C0, AX[0], AY[0]);
    cupd(x1, y1, x0, y0, C1, AX[1], AY[1]);
}

// gate on the pack bit (partner = other f32x2 lane)
__device__ __forceinline__ void gate_pck(u64 AX[2], u64 AY[2], const u64* cc) {
    Coef C = ldCoef(cc + 12);
    #pragma unroll
    for (int p = 0; p < 2; p++) {
        u64 px = swap2(AX[p]), py = swap2(AY[p]);
        cupd(AX[p], AY[p], px, py, C, AX[p], AY[p]);
    }
}

// gate on lane bit K (shfl partner lane t ^ LM)
template<int LM, int K>
__device__ __forceinline__ void gate_lane(u64 AX[2], u64 AY[2], const u64* cc, int t) {
    Coef C = ldCoef(cc + ((t >> K) & 1) * 6);
    #pragma unroll
    for (int p = 0; p < 2; p++) {
        u64 px = __shfl_xor_sync(0xffffffffu, AX[p], LM);
        u64 py = __shfl_xor_sync(0xffffffffu, AY[p], LM);
        cupd(AX[p], AY[p], px, py, C, AX[p], AY[p]);
    }
}

// Global staging float address of natural amp m (per column, 4096 floats):
// G(m) = m7 | (m2..6<<1) | (m9<<6) | (m10<<7) | (m0<<8) | (m1<<9) | (m8<<10) | (m11<<11)
__device__ __forceinline__ int Gaddr(int m) {
    return ((m >> 7) & 1) | (((m >> 2) & 0x1F) << 1) | (((m >> 9) & 1) << 6)
         | (((m >> 10) & 1) << 7) | ((m & 1) << 8) | (((m >> 1) & 1) << 9)
         | (((m >> 8) & 1) << 10) | (((m >> 11) & 1) << 11);
}

__global__ __launch_bounds__(512, 1) void fused_kernel(
    const float* __restrict__ weights, const float* __restrict__ head_w,
    const float* __restrict__ head_b, const float* __restrict__ sb,
    float* __restrict__ out, int B, int nOut)
{
    extern __shared__ char smem_raw[];
    const int t = threadIdx.x;
    const int bid = blockIdx.x;

    if (bid < 8) {
        // ================= SIM BLOCK (col = bid>>1, half r = bid&1) ========
        SimSmem* sm = (SimSmem*)smem_raw;
        const int col = bid >> 1;
        const int r = bid & 1;

        if (t < 96) {
            float phi = weights[t * 3 + 0];
            float th  = weights[t * 3 + 1];
            float om  = weights[t * 3 + 2];
            float st, ct; sincosf(th * 0.5f, &st, &ct);
            float sp, cp; sincosf((phi + om) * 0.5f, &sp, &cp);
            float sd, cd; sincosf((phi - om) * 0.5f, &sd, &cd);
            const float2 u00 = make_float2( cp * ct, -sp * ct);
            const float2 u01 = make_float2(-cd * st, -sd * st);
            const float2 u10 = make_float2( cd * st, -sd * st);
            const float2 u11 = make_float2( cp * ct,  sp * ct);
            u64* c = sm->coef + t * 18;
            c[0]  = pack2(u00.x, u00.x); c[1]  = pack2(u00.y, u00.y);
            c[2]  = pack2(-u00.y, -u00.y);
            c[3]  = pack2(u01.x, u01.x); c[4]  = pack2(u01.y, u01.y);
            c[5]  = pack2(-u01.y, -u01.y);
            c[6]  = pack2(u11.x, u11.x); c[7]  = pack2(u11.y, u11.y);
            c[8]  = pack2(-u11.y, -u11.y);
            c[9]  = pack2(u10.x, u10.x); c[10] = pack2(u10.y, u10.y);
            c[11] = pack2(-u10.y, -u10.y);
            c[12] = pack2(u00.x, u11.x); c[13] = pack2(u00.y, u11.y);
            c[14] = pack2(-u00.y, -u11.y);
            c[15] = pack2(u01.x, u10.x); c[16] = pack2(u01.y, u10.y);
            c[17] = pack2(-u01.y, -u10.y);
        }
        __syncthreads();

        // init |kj>: n11 = b0 = (col>>1)&1 -> CTA r, n10 = b1 = col&1 -> t8
        u64 AX[2] = {0ull, 0ull}, AY[2] = {0ull, 0ull};
        if (r == ((col >> 1) & 1) && t == ((col & 1) << 8))
            AX[0] = pack2(1.0f, 0.0f);

        // layer-invariant addresses
        // transpose A load: base ^ (p<<9), lane delta 256
        const int baseA = ((t & 0x7F) << 1) | ((t >> 7) & 1) | (((t >> 8) & 1) << 10);
        // transpose B load: base ^ (p<<7), lane delta 64
        const int baseB = ((t >> 5) & 1) | ((t & 0x1F) << 1)
                        | (((t >> 7) & 1) << 8) | (((t >> 8) & 1) << 9)
                        | (((t >> 6) & 1) << 10);
        // phase-3 gather base: n(t,p=0,lam=0), g = n^(n>>1), gb = G(g)
        const int nb = ((t & 0x1F) << 2) | (((t >> 5) & 0xF) << 7) | (r << 11);
        const int gb = Gaddr((nb ^ (nb >> 1)) & 0xFFF);
        // deltas: lam flip -> G(g(1)) = 256; p flip -> G(g(2)) = 768; partner ^2048

        float* fAX = (float*)sm->aX; float* fAY = (float*)sm->aY;
        float* fBX = (float*)sm->bX; float* fBY = (float*)sm->bY;
        const float* gfX = (const float*)g_sX[col];
        const float* gfY = (const float*)g_sY[col];
        u64* guX = g_sX[col]; u64* guY = g_sY[col];

        #pragma unroll 1
        for (int l = 0; l < 8; l++) {
            const u64* CG = sm->coef + l * 12 * 18;
            // ---- gates on bits 0..6 (wires 11..5) ----
            gate_pck (AX, AY, CG + 11 * 18);          // bit 0
            gate_pair(AX, AY, CG + 10 * 18);          // bit 1
            gate_lane<1, 0>(AX, AY, CG + 9 * 18, t);  // bit 2
            gate_lane<2, 1>(AX, AY, CG + 8 * 18, t);  // bit 3
            gate_lane<4, 2>(AX, AY, CG + 7 * 18, t);  // bit 4
            gate_lane<8, 3>(AX, AY, CG + 6 * 18, t);  // bit 5
            gate_lane<16, 4>(AX, AY, CG + 5 * 18, t); // bit 6
            // ---- transpose A: (lam,p) <-> (n9,n10) ----
            sm->aX[t] = AX[0]; sm->aX[512 + t] = AX[1];
            sm->aY[t] = AY[0]; sm->aY[512 + t] = AY[1];
            __syncthreads();
            #pragma unroll
            for (int p = 0; p < 2; p++) {
                int a = baseA ^ (p << 9);
                AX[p] = pack2(fAX[a], fAX[a ^ 256]);
                AY[p] = pack2(fAY[a], fAY[a ^ 256]);
            }
            gate_pck (AX, AY, CG + 2 * 18);           // bit 9 (wire 2)
            gate_pair(AX, AY, CG + 1 * 18);           // bit 10 (wire 1)
            // ---- transpose B: (lam,p) <-> (n7,n8) ----
            sm->bX[t] = AX[0]; sm->bX[512 + t] = AX[1];
            sm->bY[t] = AY[0]; sm->bY[512 + t] = AY[1];
            __syncthreads();
            #pragma unroll
            for (int p = 0; p < 2; p++) {
                int a = baseB ^ (p << 7);
                AX[p] = pack2(fBX[a], fBX[a ^ 64]);
                AY[p] = pack2(fBY[a], fBY[a ^ 64]);
            }
            gate_pck (AX, AY, CG + 4 * 18);           // bit 7 (wire 4)
            gate_pair(AX, AY, CG + 3 * 18);           // bit 8 (wire 3)
            // ---- global exchange: write halves, sync column, fused gather ----
            stcg64(&guX[(r << 10) | t], AX[0]);
            stcg64(&guX[(r << 10) | 512 | t], AX[1]);
            stcg64(&guY[(r << 10) | t], AY[0]);
            stcg64(&guY[(r << 10) | 512 | t], AY[1]);
            __threadfence();
            __syncthreads();
            if (t == 0) {
                atomicAdd(&g_cnt[col], 1u);
                while (atomicAdd(&g_cnt[col], 0u) < 2u * (unsigned)(l + 1)) { }
            }
            __syncthreads();
            {
                // wire-0 gate (bit 11): branch = r (uniform), fused with CNOT perm
                Coef C = ldCoef(CG + 0 * 18 + r * 6);
                #pragma unroll
                for (int p = 0; p < 2; p++) {
                    int a0 = gb ^ (p ? 768 : 0);
                    int a1 = a0 ^ 256;
                    u64 VX = pack2(ldcg(gfX + a0), ldcg(gfX + a1));
                    u64 VY = pack2(ldcg(gfY + a0), ldcg(gfY + a1));
                    u64 PX = pack2(ldcg(gfX + (a0 ^ 2048)), ldcg(gfX + (a1 ^ 2048)));
                    u64 PY = pack2(ldcg(gfY + (a0 ^ 2048)), ldcg(gfY + (a1 ^ 2048)));
                    cupd(VX, VY, PX, PY, C, AX[p], AY[p]);
                }
            }
        }

        // write column (natural order): n = (r<<11)|(t5..8<<7)|(t0..4<<2)|(p<<1)|lam
        #pragma unroll
        for (int p = 0; p < 2; p++) {
            float2 xs = unpack2(AX[p]), ys = unpack2(AY[p]);
            int n0 = (r << 11) | (((t >> 5) & 0xF) << 7) | ((t & 0x1F) << 2) | (p << 1);
            g_v[col][n0]     = make_float2(xs.x, ys.x);
            g_v[col][n0 | 1] = make_float2(xs.y, ys.y);
        }
        __threadfence();
        __syncthreads();
        if (t == 0) atomicAdd(&g_flag, 1);
    } else {
        // ================= OUTPUT BLOCK =================
        const int i = (bid - 8) * 512 + t;
        float s0 = 0.f, c0 = 1.f, s1 = 0.f, c1 = 1.f, hb = head_b[0];
        if (i < B) {
            float t0 = sb[i * 8 + 0], t1 = sb[i * 8 + 1];
            sincosf(t0 * 0.5f, &s0, &c0);
            sincosf(t1 * 0.5f, &s1, &c1);
        }
        float hw[12];
        #pragma unroll
        for (int w = 0; w < 12; w++) hw[w] = head_w[w];

        if (t == 0) {
            while (atomicAdd(&g_flag, 0) < 8) __nanosleep(64);
        }
        __syncthreads();
        __threadfence();

        // --- Gram: G[j][k] = sum_idx s(idx) v_j conj(v_k) ---
        float2 acc[4][4];
        #pragma unroll
        for (int a = 0; a < 4; a++)
            #pragma unroll
            for (int b = 0; b < 4; b++) acc[a][b] = make_float2(0.f, 0.f);

        for (int idx = t; idx < 4096; idx += 512) {
            float s = 0.f;
            #pragma unroll
            for (int w = 0; w < 12; w++)
                s += ((idx >> (11 - w)) & 1) ? -hw[w] : hw[w];
            float2 v[4];
            #pragma unroll
            for (int a = 0; a < 4; a++) v[a] = g_v[a][idx];
            #pragma unroll
            for (int a = 0; a < 4; a++)
                #pragma unroll
                for (int b = 0; b < 4; b++) {
                    float pr = v[a].x * v[b].x + v[a].y * v[b].y;
                    float pi = v[a].y * v[b].x - v[a].x * v[b].y;
                    acc[a][b].x += s * pr;
                    acc[a][b].y += s * pi;
                }
        }

        float* red = (float*)smem_raw;      // [16][32]
        float* Gs  = red + 16 * 32;         // [32]
        float* flat = reinterpret_cast<float*>(acc);
        const int lane = t & 31, warp = t >> 5;
        #pragma unroll
        for (int comp = 0; comp < 32; comp++) {
            float v = flat[comp];
            #pragma unroll
            for (int off = 16; off; off >>= 1)
                v += __shfl_down_sync(0xffffffff, v, off);
            if (lane == 0) red[warp * 32 + comp] = v;
        }
        __syncthreads();
        if (t < 32) {
            float v = 0.f;
            #pragma unroll
            for (int w = 0; w < 16; w++) v += red[w * 32 + t];
            Gs[t] = v;
        }
        __syncthreads();

        // self-resetting flags/counters for graph replays
        if (t == 0) {
            int d = atomicAdd(&g_done2, 1);
            if (d == nOut - 1) {
                atomicExch(&g_flag, 0);
                atomicExch(&g_done2, 0);
                #pragma unroll
                for (int cc = 0; cc < 4; cc++) atomicExch(&g_cnt[cc], 0u);
            }
        }

        // --- per-sample output: out = Re(c^H G c) + bias ---
        if (i < B) {
            float2 c[4];
            c[0] = make_float2(c0 * c1, 0.f);
            c[1] = make_float2(c0 * s1, 0.f);
            c[2] = make_float2(0.f, -s0 * c1);
            c[3] = make_float2(0.f, -s0 * s1);

            float res = hb;
            #pragma unroll
            for (int jj = 0; jj < 4; jj++)
                #pragma unroll
                for (int k = 0; k < 4; k++) {
                    float ccr = c[jj].x * c[k].x + c[jj].y * c[k].y;
                    float cci = c[jj].y * c[k].x - c[jj].x * c[k].y;
                    float gx = Gs[(jj * 4 + k) * 2];
                    float gy = Gs[(jj * 4 + k) * 2 + 1];
                    res += ccr * gx - cci * gy;
                }
            out[i] = res;
        }
    }
}

extern "C" void kernel_launch(void* const* d_in, const int* in_sizes, int n_in,
                              void* d_out, int out_size) {
    const float* state_batch = (const float*)d_in[0];  // (B, 8)
    const float* weights     = (const float*)d_in[1];  // (8, 12, 3)
    const float* head_w      = (const float*)d_in[2];  // (1, 12)
    const float* head_b      = (const float*)d_in[3];  // (1,)
    float* out = (float*)d_out;
    const int B = in_sizes[0] / 8;

    const int smem_bytes = (int)sizeof(SimSmem);
    cudaFuncSetAttribute(fused_kernel, cudaFuncAttributeMaxDynamicSharedMemorySize,
                         smem_bytes);
    const int nOut = (B + 511) / 512;
    fused_kernel<<<8 + nOut, 512, smem_bytes>>>(weights, head_w, head_b,
                                                state_batch, out, B, nOut);
}

// round 10
// speedup vs baseline: 1.1395x; 1.1395x over previous
#include <cuda_runtime.h>
#include <cuda_bf16.h>

typedef unsigned long long u64;

// Cross-block scratch (no allocations allowed -> __device__ globals)
__device__ float2 g_v[4][4096];       // 4 columns of the circuit unitary
__device__ u64 g_sX[2][4][2048];      // double-buffered per-column staging, X
__device__ u64 g_sY[2][4][2048];      // double-buffered per-column staging, Y
__device__ unsigned g_cnt[4];         // per-column layer arrival counters
__device__ unsigned g_flag = 0;       // sim-done counter (target 8)
__device__ int g_done2 = 0;           // output-blocks-passed-spin counter

// ---------------- f32x2 packed helpers ----------------
__device__ __forceinline__ u64 pack2(float x, float y) {
    u64 u; asm("mov.b64 %0, {%1,%2};" : "=l"(u) : "f"(x), "f"(y)); return u;
}
__device__ __forceinline__ float2 unpack2(u64 u) {
    float2 v; asm("mov.b64 {%0,%1}, %2;" : "=f"(v.x), "=f"(v.y) : "l"(u)); return v;
}
__device__ __forceinline__ u64 swap2(u64 u) {
    float2 v = unpack2(u); return pack2(v.y, v.x);
}
__device__ __forceinline__ u64 fma2(u64 a, u64 b, u64 c) {
    u64 d; asm("fma.rn.f32x2 %0, %1, %2, %3;" : "=l"(d) : "l"(a), "l"(b), "l"(c)); return d;
}
__device__ __forceinline__ u64 mul2(u64 a, u64 b) {
    u64 d; asm("mul.rn.f32x2 %0, %1, %2;" : "=l"(d) : "l"(a), "l"(b)); return d;
}
__device__ __forceinline__ float ldcg(const float* p) {
    float v; asm volatile("ld.global.cg.f32 %0, [%1];" : "=f"(v) : "l"(p)); return v;
}
__device__ __forceinline__ void stcg64(u64* p, u64 v) {
    asm volatile("st.global.cg.b64 [%0], %1;" :: "l"(p), "l"(v));
}
__device__ __forceinline__ void red_release_add(unsigned* p, unsigned v) {
    asm volatile("red.release.gpu.global.add.u32 [%0], %1;" :: "l"(p), "r"(v) : "memory");
}
__device__ __forceinline__ unsigned ld_acquire(const unsigned* p) {
    unsigned v;
    asm volatile("ld.acquire.gpu.global.u32 %0, [%1];" : "=r"(v) : "l"(p) : "memory");
    return v;
}

struct Coef { u64 sx, sy, nsy, ox, oy, noy; };

__device__ __forceinline__ Coef ldCoef(const u64* c) {
    Coef k;
    k.sx = c[0]; k.sy = c[1]; k.nsy = c[2];
    k.ox = c[3]; k.oy = c[4]; k.noy = c[5];
    return k;
}

// new = s*a + o*p (complex, 2 packed lanes): 8 f32x2 ops
__device__ __forceinline__ void cupd(u64 X, u64 Y, u64 PX, u64 PY, const Coef& c,
                                     u64& NX, u64& NY) {
    u64 nx = mul2(c.sx, X);
    nx = fma2(c.nsy, Y, nx);
    nx = fma2(c.ox, PX, nx);
    nx = fma2(c.noy, PY, nx);
    u64 ny = mul2(c.sx, Y);
    ny = fma2(c.sy, X, ny);
    ny = fma2(c.ox, PY, ny);
    ny = fma2(c.oy, PX, ny);
    NX = nx; NY = ny;
}

// ---------------- shared memory (dynamic, ~62KB) ----------------
struct SimSmem {
    u64 coef[96 * 18];
    u64 aX[1024]; u64 aY[1024];   // local transpose A staging
    u64 bX[1024]; u64 bY[1024];   // local transpose B staging
    u64 cX[1024]; u64 cY[1024];   // own-half mirror for self-term gather
};

// ---------------------------------------------------------------------------
// Indexing: 8 sim CTAs = 4 columns x 2 halves (identical to R9, which passed).
// Natural amp n: lam=n0, p=n1, t0..t4=n2..n6, t5..t8=n7..n10, r=n11.
// Per layer: gates bits 0..6; transpose A -> gates 9,10; transpose B -> gates
// 7,8; then exchange fusing the bit-11 gate (branch=r) with CNOT perm.
// ---------------------------------------------------------------------------

__device__ __forceinline__ void gate_pair(u64 AX[2], u64 AY[2], const u64* cc) {
    Coef C0 = ldCoef(cc);
    Coef C1 = ldCoef(cc + 6);
    u64 x0 = AX[0], y0 = AY[0], x1 = AX[1], y1 = AY[1];
    cupd(x0, y0, x1, y1, C0, AX[0], AY[0]);
    cupd(x1, y1, x0, y0, C1, AX[1], AY[1]);
}

__device__ __forceinline__ void gate_pck(u64 AX[2], u64 AY[2], const u64* cc) {
    Coef C = ldCoef(cc + 12);
    #pragma unroll
    for (int p = 0; p < 2; p++) {
        u64 px = swap2(AX[p]), py = swap2(AY[p]);
        cupd(AX[p], AY[p], px, py, C, AX[p], AY[p]);
    }
}

template<int LM, int K>
__device__ __forceinline__ void gate_lane(u64 AX[2], u64 AY[2], const u64* cc, int t) {
    Coef C = ldCoef(cc + ((t >> K) & 1) * 6);
    #pragma unroll
    for (int p = 0; p < 2; p++) {
        u64 px = __shfl_xor_sync(0xffffffffu, AX[p], LM);
        u64 py = __shfl_xor_sync(0xffffffffu, AY[p], LM);
        cupd(AX[p], AY[p], px, py, C, AX[p], AY[p]);
    }
}

// Global/smem staging float address of natural amp m (per column):
// G(m) = m7 | (m2..6<<1) | (m9<<6) | (m10<<7) | (m0<<8) | (m1<<9) | (m8<<10) | (m11<<11)
__device__ __forceinline__ int Gaddr(int m) {
    return ((m >> 7) & 1) | (((m >> 2) & 0x1F) << 1) | (((m >> 9) & 1) << 6)
         | (((m >> 10) & 1) << 7) | ((m & 1) << 8) | (((m >> 1) & 1) << 9)
         | (((m >> 8) & 1) << 10) | (((m >> 11) & 1) << 11);
}

__global__ __launch_bounds__(512, 1) void fused_kernel(
    const float* __restrict__ weights, const float* __restrict__ head_w,
    const float* __restrict__ head_b, const float* __restrict__ sb,
    float* __restrict__ out, int B, int nOut)
{
    extern __shared__ char smem_raw[];
    const int t = threadIdx.x;
    const int bid = blockIdx.x;

    if (bid < 8) {
        // ================= SIM BLOCK (col = bid>>1, half r = bid&1) ========
        SimSmem* sm = (SimSmem*)smem_raw;
        const int col = bid >> 1;
        const int r = bid & 1;

        if (t < 96) {
            float phi = weights[t * 3 + 0];
            float th  = weights[t * 3 + 1];
            float om  = weights[t * 3 + 2];
            float st, ct; sincosf(th * 0.5f, &st, &ct);
            float sp, cp; sincosf((phi + om) * 0.5f, &sp, &cp);
            float sd, cd; sincosf((phi - om) * 0.5f, &sd, &cd);
            const float2 u00 = make_float2( cp * ct, -sp * ct);
            const float2 u01 = make_float2(-cd * st, -sd * st);
            const float2 u10 = make_float2( cd * st, -sd * st);
            const float2 u11 = make_float2( cp * ct,  sp * ct);
            u64* c = sm->coef + t * 18;
            c[0]  = pack2(u00.x, u00.x); c[1]  = pack2(u00.y, u00.y);
            c[2]  = pack2(-u00.y, -u00.y);
            c[3]  = pack2(u01.x, u01.x); c[4]  = pack2(u01.y, u01.y);
            c[5]  = pack2(-u01.y, -u01.y);
            c[6]  = pack2(u11.x, u11.x); c[7]  = pack2(u11.y, u11.y);
            c[8]  = pack2(-u11.y, -u11.y);
            c[9]  = pack2(u10.x, u10.x); c[10] = pack2(u10.y, u10.y);
            c[11] = pack2(-u10.y, -u10.y);
            c[12] = pack2(u00.x, u11.x); c[13] = pack2(u00.y, u11.y);
            c[14] = pack2(-u00.y, -u11.y);
            c[15] = pack2(u01.x, u10.x); c[16] = pack2(u01.y, u10.y);
            c[17] = pack2(-u01.y, -u10.y);
        }
        __syncthreads();

        // init |kj>: n11 = b0 = (col>>1)&1 -> CTA r, n10 = b1 = col&1 -> t8
        u64 AX[2] = {0ull, 0ull}, AY[2] = {0ull, 0ull};
        if (r == ((col >> 1) & 1) && t == ((col & 1) << 8))
            AX[0] = pack2(1.0f, 0.0f);

        // layer-invariant addresses (verbatim R9)
        const int baseA = ((t & 0x7F) << 1) | ((t >> 7) & 1) | (((t >> 8) & 1) << 10);
        const int baseB = ((t >> 5) & 1) | ((t & 0x1F) << 1)
                        | (((t >> 7) & 1) << 8) | (((t >> 8) & 1) << 9)
                        | (((t >> 6) & 1) << 10);
        const int nb = ((t & 0x1F) << 2) | (((t >> 5) & 0xF) << 7) | (r << 11);
        const int gb = Gaddr((nb ^ (nb >> 1)) & 0xFFF);

        float* fAX = (float*)sm->aX; float* fAY = (float*)sm->aY;
        float* fBX = (float*)sm->bX; float* fBY = (float*)sm->bY;
        float* csX = (float*)sm->cX; float* csY = (float*)sm->cY;

        #pragma unroll 1
        for (int l = 0; l < 8; l++) {
            const u64* CG = sm->coef + l * 12 * 18;
            // ---- gates on bits 0..6 (wires 11..5) ----
            gate_pck (AX, AY, CG + 11 * 18);
            gate_pair(AX, AY, CG + 10 * 18);
            gate_lane<1, 0>(AX, AY, CG + 9 * 18, t);
            gate_lane<2, 1>(AX, AY, CG + 8 * 18, t);
            gate_lane<4, 2>(AX, AY, CG + 7 * 18, t);
            gate_lane<8, 3>(AX, AY, CG + 6 * 18, t);
            gate_lane<16, 4>(AX, AY, CG + 5 * 18, t);
            // ---- transpose A: (lam,p) <-> (n9,n10) ----
            sm->aX[t] = AX[0]; sm->aX[512 + t] = AX[1];
            sm->aY[t] = AY[0]; sm->aY[512 + t] = AY[1];
            __syncthreads();
            #pragma unroll
            for (int p = 0; p < 2; p++) {
                int a = baseA ^ (p << 9);
                AX[p] = pack2(fAX[a], fAX[a ^ 256]);
                AY[p] = pack2(fAY[a], fAY[a ^ 256]);
            }
            gate_pck (AX, AY, CG + 2 * 18);
            gate_pair(AX, AY, CG + 1 * 18);
            // ---- transpose B: (lam,p) <-> (n7,n8) ----
            sm->bX[t] = AX[0]; sm->bX[512 + t] = AX[1];
            sm->bY[t] = AY[0]; sm->bY[512 + t] = AY[1];
            __syncthreads();
            #pragma unroll
            for (int p = 0; p < 2; p++) {
                int a = baseB ^ (p << 7);
                AX[p] = pack2(fBX[a], fBX[a ^ 64]);
                AY[p] = pack2(fBY[a], fBY[a ^ 64]);
            }
            gate_pck (AX, AY, CG + 4 * 18);
            gate_pair(AX, AY, CG + 3 * 18);
            // ---- exchange: own half to smem(self) + global(peer) ----
            u64* guX = g_sX[l & 1][col];
            u64* guY = g_sY[l & 1][col];
            const float* gfX = (const float*)guX;
            const float* gfY = (const float*)guY;
            stcg64(&guX[(r << 10) | t], AX[0]);
            stcg64(&guX[(r << 10) | 512 | t], AX[1]);
            stcg64(&guY[(r << 10) | t], AY[0]);
            stcg64(&guY[(r << 10) | 512 | t], AY[1]);
            sm->cX[t] = AX[0]; sm->cX[512 + t] = AX[1];
            sm->cY[t] = AY[0]; sm->cY[512 + t] = AY[1];
            __syncthreads();
            if (t == 0) red_release_add(&g_cnt[col], 1u);
            // self terms (own half, from smem) while the release propagates
            Coef C = ldCoef(CG + 0 * 18 + r * 6);
            u64 TX[2], TY[2];
            int a0s[2], a1s[2];
            #pragma unroll
            for (int p = 0; p < 2; p++) {
                int a0 = gb ^ (p ? 768 : 0);
                int a1 = a0 ^ 256;
                a0s[p] = a0; a1s[p] = a1;
                u64 VX = pack2(csX[a0 & 2047], csX[a1 & 2047]);
                u64 VY = pack2(csY[a0 & 2047], csY[a1 & 2047]);
                TX[p] = fma2(C.nsy, VY, mul2(C.sx, VX));
                TY[p] = fma2(C.sy, VX, mul2(C.sx, VY));
            }
            if (t == 0) {
                unsigned tgt = 2u * (unsigned)(l + 1);
                while (ld_acquire(&g_cnt[col]) < tgt) { }
            }
            __syncthreads();
            // peer terms (other half, via L2)
            #pragma unroll
            for (int p = 0; p < 2; p++) {
                int a0 = a0s[p] ^ 2048, a1 = a1s[p] ^ 2048;
                u64 PX = pack2(ldcg(gfX + a0), ldcg(gfX + a1));
                u64 PY = pack2(ldcg(gfY + a0), ldcg(gfY + a1));
                AX[p] = fma2(C.noy, PY, fma2(C.ox, PX, TX[p]));
                AY[p] = fma2(C.oy, PX, fma2(C.ox, PY, TY[p]));
            }
        }

        // write column (natural order)
        #pragma unroll
        for (int p = 0; p < 2; p++) {
            float2 xs = unpack2(AX[p]), ys = unpack2(AY[p]);
            int n0 = (r << 11) | (((t >> 5) & 0xF) << 7) | ((t & 0x1F) << 2) | (p << 1);
            g_v[col][n0]     = make_float2(xs.x, ys.x);
            g_v[col][n0 | 1] = make_float2(xs.y, ys.y);
        }
        __syncthreads();
        if (t == 0) red_release_add(&g_flag, 1u);
    } else {
        // ================= OUTPUT BLOCK =================
        const int i = (bid - 8) * 512 + t;
        float s0 = 0.f, c0 = 1.f, s1 = 0.f, c1 = 1.f, hb = head_b[0];
        if (i < B) {
            float t0 = sb[i * 8 + 0], t1 = sb[i * 8 + 1];
            sincosf(t0 * 0.5f, &s0, &c0);
            sincosf(t1 * 0.5f, &s1, &c1);
        }
        float hw[12];
        #pragma unroll
        for (int w = 0; w < 12; w++) hw[w] = head_w[w];

        if (t == 0) {
            while (ld_acquire(&g_flag) < 8u) __nanosleep(32);
        }
        __syncthreads();

        // --- Gram: G[j][k] = sum_idx s(idx) v_j conj(v_k) ---
        float2 acc[4][4];
        #pragma unroll
        for (int a = 0; a < 4; a++)
            #pragma unroll
            for (int b = 0; b < 4; b++) acc[a][b] = make_float2(0.f, 0.f);

        for (int idx = t; idx < 4096; idx += 512) {
            float s = 0.f;
            #pragma unroll
            for (int w = 0; w < 12; w++)
                s += ((idx >> (11 - w)) & 1) ? -hw[w] : hw[w];
            float2 v[4];
            #pragma unroll
            for (int a = 0; a < 4; a++) v[a] = g_v[a][idx];
            #pragma unroll
            for (int a = 0; a < 4; a++)
                #pragma unroll
                for (int b = 0; b < 4; b++) {
                    float pr = v[a].x * v[b].x + v[a].y * v[b].y;
                    float pi = v[a].y * v[b].x - v[a].x * v[b].y;
                    acc[a][b].x += s * pr;
                    acc[a][b].y += s * pi;
                }
        }

        float* red = (float*)smem_raw;      // [16][32]
        float* Gs  = red + 16 * 32;         // [32]
        float* flat = reinterpret_cast<float*>(acc);
        const int lane = t & 31, warp = t >> 5;
        #pragma unroll
        for (int comp = 0; comp < 32; comp++) {
            float v = flat[comp];
            #pragma unroll
            for (int off = 16; off; off >>= 1)
                v += __shfl_down_sync(0xffffffff, v, off);
            if (lane == 0) red[warp * 32 + comp] = v;
        }
        __syncthreads();
        if (t < 32) {
            float v = 0.f;
            #pragma unroll
            for (int w = 0; w < 16; w++) v += red[w * 32 + t];
            Gs[t] = v;
        }
        __syncthreads();

        // self-resetting flags/counters for graph replays
        if (t == 0) {
            int d = atomicAdd(&g_done2, 1);
            if (d == nOut - 1) {
                atomicExch(&g_flag, 0u);
                atomicExch(&g_done2, 0);
                #pragma unroll
                for (int cc = 0; cc < 4; cc++) atomicExch(&g_cnt[cc], 0u);
            }
        }

        // --- per-sample output: out = Re(c^H G c) + bias ---
        if (i < B) {
            float2 c[4];
            c[0] = make_float2(c0 * c1, 0.f);
            c[1] = make_float2(c0 * s1, 0.f);
            c[2] = make_float2(0.f, -s0 * c1);
            c[3] = make_float2(0.f, -s0 * s1);

            float res = hb;
            #pragma unroll
            for (int jj = 0; jj < 4; jj++)
                #pragma unroll
                for (int k = 0; k < 4; k++) {
                    float ccr = c[jj].x * c[k].x + c[jj].y * c[k].y;
                    float cci = c[jj].y * c[k].x - c[jj].x * c[k].y;
                    float gx = Gs[(jj * 4 + k) * 2];
                    float gy = Gs[(jj * 4 + k) * 2 + 1];
                    res += ccr * gx - cci * gy;
                }
            out[i] = res;
        }
    }
}

extern "C" void kernel_launch(void* const* d_in, const int* in_sizes, int n_in,
                              void* d_out, int out_size) {
    const float* state_batch = (const float*)d_in[0];  // (B, 8)
    const float* weights     = (const float*)d_in[1];  // (8, 12, 3)
    const float* head_w      = (const float*)d_in[2];  // (1, 12)
    const float* head_b      = (const float*)d_in[3];  // (1,)
    float* out = (float*)d_out;
    const int B = in_sizes[0] / 8;

    const int smem_bytes = (int)sizeof(SimSmem);
    cudaFuncSetAttribute(fused_kernel, cudaFuncAttributeMaxDynamicSharedMemorySize,
                         smem_bytes);
    const int nOut = (B + 511) / 512;
    fused_kernel<<<8 + nOut, 512, smem_bytes>>>(weights, head_w, head_b,
                                                state_batch, out, B, nOut);
}

// round 12
// speedup vs baseline: 1.2885x; 1.1308x over previous
#include <cuda_runtime.h>
#include <cuda_bf16.h>
#include <cstdint>

typedef unsigned long long u64;

// Cross-block scratch (no allocations allowed -> __device__ globals)
__device__ float2 g_v[4][4096];       // 4 columns of the circuit unitary
__device__ u64 g_sX[2][4][2048];      // double-buffered per-column staging, X
__device__ u64 g_sY[2][4][2048];      // double-buffered per-column staging, Y
__device__ unsigned g_flag = 0;       // sim-done counter (target 8)
__device__ int g_done2 = 0;           // output-blocks-passed-spin counter

// ---------------- f32x2 packed helpers ----------------
__device__ __forceinline__ u64 pack2(float x, float y) {
    u64 u; asm("mov.b64 %0, {%1,%2};" : "=l"(u) : "f"(x), "f"(y)); return u;
}
__device__ __forceinline__ float2 unpack2(u64 u) {
    float2 v; asm("mov.b64 {%0,%1}, %2;" : "=f"(v.x), "=f"(v.y) : "l"(u)); return v;
}
__device__ __forceinline__ u64 swap2(u64 u) {
    float2 v = unpack2(u); return pack2(v.y, v.x);
}
__device__ __forceinline__ u64 fma2(u64 a, u64 b, u64 c) {
    u64 d; asm("fma.rn.f32x2 %0, %1, %2, %3;" : "=l"(d) : "l"(a), "l"(b), "l"(c)); return d;
}
__device__ __forceinline__ u64 mul2(u64 a, u64 b) {
    u64 d; asm("mul.rn.f32x2 %0, %1, %2;" : "=l"(d) : "l"(a), "l"(b)); return d;
}
__device__ __forceinline__ float ldcg(const float* p) {
    float v; asm volatile("ld.global.cg.f32 %0, [%1];" : "=f"(v) : "l"(p)); return v;
}
__device__ __forceinline__ void stcg64(u64* p, u64 v) {
    asm volatile("st.global.cg.b64 [%0], %1;" :: "l"(p), "l"(v));
}
__device__ __forceinline__ void red_release_add(unsigned* p, unsigned v) {
    asm volatile("red.release.gpu.global.add.u32 [%0], %1;" :: "l"(p), "r"(v) : "memory");
}
__device__ __forceinline__ unsigned ld_acquire(const unsigned* p) {
    unsigned v;
    asm volatile("ld.acquire.gpu.global.u32 %0, [%1];" : "=r"(v) : "l"(p) : "memory");
    return v;
}

// ---------------- cluster / mbarrier helpers ----------------
__device__ __forceinline__ uint32_t smem32(const void* p) {
    uint32_t a;
    asm("{ .reg .u64 t; cvta.to.shared.u64 t, %1; cvt.u32.u64 %0, t; }"
        : "=r"(a) : "l"(p));
    return a;
}
__device__ __forceinline__ void mbar_init(uint32_t a, unsigned cnt) {
    asm volatile("mbarrier.init.shared.b64 [%0], %1;" :: "r"(a), "r"(cnt) : "memory");
}
// arrive (release, cluster scope) on the SAME smem offset in the peer CTA
__device__ __forceinline__ void mbar_arrive_peer(uint32_t a, unsigned peer) {
    asm volatile(
        "{\n\t.reg .b32 ra;\n\t"
        "mapa.shared::cluster.u32 ra, %0, %1;\n\t"
        "mbarrier.arrive.release.cluster.shared::cluster.b64 _, [ra];\n\t}"
        :: "r"(a), "r"(peer) : "memory");
}
// parity wait with cluster-scope acquire (orders peer's prior global stores)
__device__ __forceinline__ void mbar_wait(uint32_t a, unsigned parity) {
    asm volatile(
        "{\n\t.reg .pred P;\n\t"
        "W%=:\n\t"
        "mbarrier.try_wait.parity.acquire.cluster.shared::cta.b64 P, [%0], %1;\n\t"
        "@P bra.uni D%=;\n\t"
        "bra.uni W%=;\n\t"
        "D%=:\n\t}"
        :: "r"(a), "r"(parity) : "memory");
}
#define CLUSTER_ARRIVE() asm volatile("barrier.cluster.arrive.aligned;" ::: "memory")
#define CLUSTER_WAIT()   asm volatile("barrier.cluster.wait.aligned;" ::: "memory")

struct Coef { u64 sx, sy, nsy, ox, oy, noy; };

// 16B-aligned blocks (stride 144B per gate, sub-blocks at +0/+48/+96) -> LDS.128
__device__ __forceinline__ Coef ldCoef(const u64* c) {
    const ulonglong2* v = (const ulonglong2*)c;
    ulonglong2 a = v[0], b = v[1], d = v[2];
    Coef k;
    k.sx = a.x; k.sy = a.y; k.nsy = b.x;
    k.ox = b.y; k.oy = d.x; k.noy = d.y;
    return k;
}

// new = s*a + o*p (complex, 2 packed lanes): 8 f32x2 ops
__device__ __forceinline__ void cupd(u64 X, u64 Y, u64 PX, u64 PY, const Coef& c,
                                     u64& NX, u64& NY) {
    u64 nx = mul2(c.sx, X);
    nx = fma2(c.nsy, Y, nx);
    nx = fma2(c.ox, PX, nx);
    nx = fma2(c.noy, PY, nx);
    u64 ny = mul2(c.sx, Y);
    ny = fma2(c.sy, X, ny);
    ny = fma2(c.ox, PY, ny);
    ny = fma2(c.oy, PX, ny);
    NX = nx; NY = ny;
}

// ---------------- shared memory (dynamic, ~63KB) ----------------
struct SimSmem {
    u64 coef[96 * 18];
    u64 aX[1024]; u64 aY[1024];   // local transpose A staging
    u64 bX[1024]; u64 bY[1024];   // local transpose B staging
    u64 cX[1024]; u64 cY[1024];   // own-half mirror for self-term gather
    u64 mbar[2];                  // double-buffered cross-CTA mbarriers
};

// ---------------------------------------------------------------------------
// Indexing: 8 sim CTAs = 4 columns x 2 halves (identical to R10, which passed).
// Natural amp n: lam=n0, p=n1, t0..t4=n2..n6, t5..t8=n7..n10, r=n11.
// Per layer: gates bits 0..6; transpose A -> gates 9,10; transpose B -> gates
// 7,8; then exchange fusing the bit-11 gate (branch=r) with CNOT perm.
// ---------------------------------------------------------------------------

__device__ __forceinline__ void gate_pair(u64 AX[2], u64 AY[2], const u64* cc) {
    Coef C0 = ldCoef(cc);
    Coef C1 = ldCoef(cc + 6);
    u64 x0 = AX[0], y0 = AY[0], x1 = AX[1], y1 = AY[1];
    cupd(x0, y0, x1, y1, C0, AX[0], AY[0]);
    cupd(x1, y1, x0, y0, C1, AX[1], AY[1]);
}

__device__ __forceinline__ void gate_pck(u64 AX[2], u64 AY[2], const u64* cc) {
    Coef C = ldCoef(cc + 12);
    #pragma unroll
    for (int p = 0; p < 2; p++) {
        u64 px = swap2(AX[p]), py = swap2(AY[p]);
        cupd(AX[p], AY[p], px, py, C, AX[p], AY[p]);
    }
}

template<int LM, int K>
__device__ __forceinline__ void gate_lane(u64 AX[2], u64 AY[2], const u64* cc, int t) {
    Coef C = ldCoef(cc + ((t >> K) & 1) * 6);
    #pragma unroll
    for (int p = 0; p < 2; p++) {
        u64 px = __shfl_xor_sync(0xffffffffu, AX[p], LM);
        u64 py = __shfl_xor_sync(0xffffffffu, AY[p], LM);
        cupd(AX[p], AY[p], px, py, C, AX[p], AY[p]);
    }
}

// Global/smem staging float address of natural amp m (per column):
// G(m) = m7 | (m2..6<<1) | (m9<<6) | (m10<<7) | (m0<<8) | (m1<<9) | (m8<<10) | (m11<<11)
__device__ __forceinline__ int Gaddr(int m) {
    return ((m >> 7) & 1) | (((m >> 2) & 0x1F) << 1) | (((m >> 9) & 1) << 6)
         | (((m >> 10) & 1) << 7) | ((m & 1) << 8) | (((m >> 1) & 1) << 9)
         | (((m >> 8) & 1) << 10) | (((m >> 11) & 1) << 11);
}

__global__ __launch_bounds__(512, 1) __cluster_dims__(2, 1, 1)
void fused_kernel(
    const float* __restrict__ weights, const float* __restrict__ head_w,
    const float* __restrict__ head_b, const float* __restrict__ sb,
    float* __restrict__ out, int B, int nOut)
{
    extern __shared__ char smem_raw[];
    const int t = threadIdx.x;
    const int bid = blockIdx.x;

    if (bid < 8) {
        // ================= SIM BLOCK (col = bid>>1, half r = bid&1) ========
        SimSmem* sm = (SimSmem*)smem_raw;
        const int col = bid >> 1;
        const int r = bid & 1;
        const unsigned peer = 1u - (unsigned)r;   // cluster rank of the other half
        const uint32_t mb0 = smem32(&sm->mbar[0]);
        const uint32_t mb1 = smem32(&sm->mbar[1]);

        if (t < 96) {
            float phi = weights[t * 3 + 0];
            float th  = weights[t * 3 + 1];
            float om  = weights[t * 3 + 2];
            float st, ct; sincosf(th * 0.5f, &st, &ct);
            float sp, cp; sincosf((phi + om) * 0.5f, &sp, &cp);
            float sd, cd; sincosf((phi - om) * 0.5f, &sd, &cd);
            const float2 u00 = make_float2( cp * ct, -sp * ct);
            const float2 u01 = make_float2(-cd * st, -sd * st);
            const float2 u10 = make_float2( cd * st, -sd * st);
            const float2 u11 = make_float2( cp * ct,  sp * ct);
            u64* c = sm->coef + t * 18;
            c[0]  = pack2(u00.x, u00.x); c[1]  = pack2(u00.y, u00.y);
            c[2]  = pack2(-u00.y, -u00.y);
            c[3]  = pack2(u01.x, u01.x); c[4]  = pack2(u01.y, u01.y);
            c[5]  = pack2(-u01.y, -u01.y);
            c[6]  = pack2(u11.x, u11.x); c[7]  = pack2(u11.y, u11.y);
            c[8]  = pack2(-u11.y, -u11.y);
            c[9]  = pack2(u10.x, u10.x); c[10] = pack2(u10.y, u10.y);
            c[11] = pack2(-u10.y, -u10.y);
            c[12] = pack2(u00.x, u11.x); c[13] = pack2(u00.y, u11.y);
            c[14] = pack2(-u00.y, -u11.y);
            c[15] = pack2(u01.x, u10.x); c[16] = pack2(u01.y, u10.y);
            c[17] = pack2(-u01.y, -u10.y);
        }
        if (t == 0) { mbar_init(mb0, 1); mbar_init(mb1, 1); }
        __syncthreads();
        // both halves' mbarriers must be live before any cross-CTA arrive
        CLUSTER_ARRIVE();
        CLUSTER_WAIT();

        // init |kj>: n11 = b0 = (col>>1)&1 -> CTA r, n10 = b1 = col&1 -> t8
        u64 AX[2] = {0ull, 0ull}, AY[2] = {0ull, 0ull};
        if (r == ((col >> 1) & 1) && t == ((col & 1) << 8))
            AX[0] = pack2(1.0f, 0.0f);

        // layer-invariant addresses (verbatim R10)
        const int baseA = ((t & 0x7F) << 1) | ((t >> 7) & 1) | (((t >> 8) & 1) << 10);
        const int baseB = ((t >> 5) & 1) | ((t & 0x1F) << 1)
                        | (((t >> 7) & 1) << 8) | (((t >> 8) & 1) << 9)
                        | (((t >> 6) & 1) << 10);
        const int nb = ((t & 0x1F) << 2) | (((t >> 5) & 0xF) << 7) | (r << 11);
        const int gb = Gaddr((nb ^ (nb >> 1)) & 0xFFF);

        float* fAX = (float*)sm->aX; float* fAY = (float*)sm->aY;
        float* fBX = (float*)sm->bX; float* fBY = (float*)sm->bY;
        float* csX = (float*)sm->cX; float* csY = (float*)sm->cY;

        #pragma unroll 1
        for (int l = 0; l < 8; l++) {
            const u64* CG = sm->coef + l * 12 * 18;
            // ---- gates on bits 0..6 (wires 11..5) ----
            gate_pck (AX, AY, CG + 11 * 18);
            gate_pair(AX, AY, CG + 10 * 18);
            gate_lane<1, 0>(AX, AY, CG + 9 * 18, t);
            gate_lane<2, 1>(AX, AY, CG + 8 * 18, t);
            gate_lane<4, 2>(AX, AY, CG + 7 * 18, t);
            gate_lane<8, 3>(AX, AY, CG + 6 * 18, t);
            gate_lane<16, 4>(AX, AY, CG + 5 * 18, t);
            // ---- transpose A: (lam,p) <-> (n9,n10) ----
            sm->aX[t] = AX[0]; sm->aX[512 + t] = AX[1];
            sm->aY[t] = AY[0]; sm->aY[512 + t] = AY[1];
            __syncthreads();
            #pragma unroll
            for (int p = 0; p < 2; p++) {
                int a = baseA ^ (p << 9);
                AX[p] = pack2(fAX[a], fAX[a ^ 256]);
                AY[p] = pack2(fAY[a], fAY[a ^ 256]);
            }
            gate_pck (AX, AY, CG + 2 * 18);
            gate_pair(AX, AY, CG + 1 * 18);
            // ---- transpose B: (lam,p) <-> (n7,n8) ----
            sm->bX[t] = AX[0]; sm->bX[512 + t] = AX[1];
            sm->bY[t] = AY[0]; sm->bY[512 + t] = AY[1];
            __syncthreads();
            #pragma unroll
            for (int p = 0; p < 2; p++) {
                int a = baseB ^ (p << 7);
                AX[p] = pack2(fBX[a], fBX[a ^ 64]);
                AY[p] = pack2(fBY[a], fBY[a ^ 64]);
            }
            gate_pck (AX, AY, CG + 4 * 18);
            gate_pair(AX, AY, CG + 3 * 18);
            // ---- exchange: own half to smem(self) + L2(peer), mbarrier sync ----
            u64* guX = g_sX[l & 1][col];
            u64* guY = g_sY[l & 1][col];
            const float* gfX = (const float*)guX;
            const float* gfY = (const float*)guY;
            stcg64(&guX[(r << 10) | t], AX[0]);
            stcg64(&guX[(r << 10) | 512 | t], AX[1]);
            stcg64(&guY[(r << 10) | t], AY[0]);
            stcg64(&guY[(r << 10) | 512 | t], AY[1]);
            sm->cX[t] = AX[0]; sm->cX[512 + t] = AX[1];
            sm->cY[t] = AY[0]; sm->cY[512 + t] = AY[1];
            __syncthreads();
            const uint32_t mb = (l & 1) ? mb1 : mb0;
            if (t == 0) mbar_arrive_peer(mb, peer);   // release: publishes .cg stores
            // self terms (own half, from smem) in the arrive/wait shadow
            Coef C = ldCoef(CG + 0 * 18 + r * 6);
            u64 TX[2], TY[2];
            int a0s[2], a1s[2];
            #pragma unroll
            for (int p = 0; p < 2; p++) {
                int a0 = gb ^ (p ? 768 : 0);
                int a1 = a0 ^ 256;
                a0s[p] = a0; a1s[p] = a1;
                u64 VX = pack2(csX[a0 & 2047], csX[a1 & 2047]);
                u64 VY = pack2(csY[a0 & 2047], csY[a1 & 2047]);
                TX[p] = fma2(C.nsy, VY, mul2(C.sx, VX));
                TY[p] = fma2(C.sy, VX, mul2(C.sx, VY));
            }
            mbar_wait(mb, (unsigned)((l >> 1) & 1));  // acquire: peer stores visible
            // peer terms (other half, via L2)
            #pragma unroll
            for (int p = 0; p < 2; p++) {
                int a0 = a0s[p] ^ 2048, a1 = a1s[p] ^ 2048;
                u64 PX = pack2(ldcg(gfX + a0), ldcg(gfX + a1));
                u64 PY = pack2(ldcg(gfY + a0), ldcg(gfY + a1));
                AX[p] = fma2(C.noy, PY, fma2(C.ox, PX, TX[p]));
                AY[p] = fma2(C.oy, PX, fma2(C.ox, PY, TY[p]));
            }
        }

        // write column (natural order)
        #pragma unroll
        for (int p = 0; p < 2; p++) {
            float2 xs = unpack2(AX[p]), ys = unpack2(AY[p]);
            int n0 = (r << 11) | (((t >> 5) & 0xF) << 7) | ((t & 0x1F) << 2) | (p << 1);
            g_v[col][n0]     = make_float2(xs.x, ys.x);
            g_v[col][n0 | 1] = make_float2(xs.y, ys.y);
        }
        __syncthreads();
        if (t == 0) red_release_add(&g_flag, 1u);
        // don't exit while the peer may still arrive/read
        CLUSTER_ARRIVE();
        CLUSTER_WAIT();
    } else {
        // ================= OUTPUT BLOCK =================
        const int i = (bid - 8) * 512 + t;
        float s0 = 0.f, c0 = 1.f, s1 = 0.f, c1 = 1.f, hb = head_b[0];
        if (i < B) {
            float t0 = sb[i * 8 + 0], t1 = sb[i * 8 + 1];
            sincosf(t0 * 0.5f, &s0, &c0);
            sincosf(t1 * 0.5f, &s1, &c1);
        }
        float hw[12];
        #pragma unroll
        for (int w = 0; w < 12; w++) hw[w] = head_w[w];

        if (t == 0) {
            while (ld_acquire(&g_flag) < 8u) __nanosleep(32);
        }
        __syncthreads();

        // --- Gram: G[j][k] = sum_idx s(idx) v_j conj(v_k) ---
        float2 acc[4][4];
        #pragma unroll
        for (int a = 0; a < 4; a++)
            #pragma unroll
            for (int b = 0; b < 4; b++) acc[a][b] = make_float2(0.f, 0.f);

        for (int idx = t; idx < 4096; idx += 512) {
            float s = 0.f;
            #pragma unroll
            for (int w = 0; w < 12; w++)
                s += ((idx >> (11 - w)) & 1) ? -hw[w] : hw[w];
            float2 v[4];
            #pragma unroll
            for (int a = 0; a < 4; a++) v[a] = g_v[a][idx];
            #pragma unroll
            for (int a = 0; a < 4; a++)
                #pragma unroll
                for (int b = 0; b < 4; b++) {
                    float pr = v[a].x * v[b].x + v[a].y * v[b].y;
                    float pi = v[a].y * v[b].x - v[a].x * v[b].y;
                    acc[a][b].x += s * pr;
                    acc[a][b].y += s * pi;
                }
        }

        float* red = (float*)smem_raw;      // [16][32]
        float* Gs  = red + 16 * 32;         // [32]
        float* flat = reinterpret_cast<float*>(acc);
        const int lane = t & 31, warp = t >> 5;
        #pragma unroll
        for (int comp = 0; comp < 32; comp++) {
            float v = flat[comp];
            #pragma unroll
            for (int off = 16; off; off >>= 1)
                v += __shfl_down_sync(0xffffffff, v, off);
            if (lane == 0) red[warp * 32 + comp] = v;
        }
        __syncthreads();
        if (t < 32) {
            float v = 0.f;
            #pragma unroll
            for (int w = 0; w < 16; w++) v += red[w * 32 + t];
            Gs[t] = v;
        }
        __syncthreads();

        // self-resetting flags for graph replays
        if (t == 0) {
            int d = atomicAdd(&g_done2, 1);
            if (d == nOut - 1) {
                atomicExch(&g_flag, 0u);
                atomicExch(&g_done2, 0);
            }
        }

        // --- per-sample output: out = Re(c^H G c) + bias ---
        if (i < B) {
            float2 c[4];
            c[0] = make_float2(c0 * c1, 0.f);
            c[1] = make_float2(c0 * s1, 0.f);
            c[2] = make_float2(0.f, -s0 * c1);
            c[3] = make_float2(0.f, -s0 * s1);

            float res = hb;
            #pragma unroll
            for (int jj = 0; jj < 4; jj++)
                #pragma unroll
                for (int k = 0; k < 4; k++) {
                    float ccr = c[jj].x * c[k].x + c[jj].y * c[k].y;
                    float cci = c[jj].y * c[k].x - c[jj].x * c[k].y;
                    float gx = Gs[(jj * 4 + k) * 2];
                    float gy = Gs[(jj * 4 + k) * 2 + 1];
                    res += ccr * gx - cci * gy;
                }
            out[i] = res;
        }
    }
}

extern "C" void kernel_launch(void* const* d_in, const int* in_sizes, int n_in,
                              void* d_out, int out_size) {
    const float* state_batch = (const float*)d_in[0];  // (B, 8)
    const float* weights     = (const float*)d_in[1];  // (8, 12, 3)
    const float* head_w      = (const float*)d_in[2];  // (1, 12)
    const float* head_b      = (const float*)d_in[3];  // (1,)
    float* out = (float*)d_out;
    const int B = in_sizes[0] / 8;

    const int smem_bytes = (int)sizeof(SimSmem);
    cudaFuncSetAttribute(fused_kernel, cudaFuncAttributeMaxDynamicSharedMemorySize,
                         smem_bytes);
    int nOut = (B + 511) / 512;
    nOut += (nOut & 1);   // grid must be even for cluster_dims (2,1,1)
    fused_kernel<<<8 + nOut, 512, smem_bytes>>>(weights, head_w, head_b,
                                                state_batch, out, B, nOut);
}